// round 7
// baseline (speedup 1.0000x reference)
#include <cuda_runtime.h>
#include <math.h>

#define BB  256
#define GG  2048
#define FF  128
#define RNN 512
#define KK  128

// Scratch (no allocation allowed) ------------------------------------------
__device__ float g_scorer[BB * FF];
__device__ float g_scores[BB * GG];

// --------------------------------------------------------------------------
// K1: scorer[b,f] = tanh(h_t[b,:] @ W[:,f] + bias[f]) / ||tanh||
//     128 blocks x 256 threads, 2 batches/block, W staged via smem chunks
// --------------------------------------------------------------------------
__global__ void k1_scorer(const float* __restrict__ h_t,
                          const float* __restrict__ W,
                          const float* __restrict__ bmap) {
    int tid = threadIdx.x;               // 256
    int bq = tid >> 7, f = tid & 127;
    int b0 = blockIdx.x * 2;
    __shared__ float Ws[64 * 128];
    __shared__ float hs[2 * RNN];
    __shared__ float red2[8];
    for (int i = tid; i < 2 * RNN; i += 256)
        hs[i] = h_t[b0 * RNN + i];
    float acc = bmap[f];
    float4* Ws4 = reinterpret_cast<float4*>(Ws);
    for (int c = 0; c < RNN / 64; ++c) {
        __syncthreads();
        const float4* W4 = reinterpret_cast<const float4*>(W + c * 64 * 128);
#pragma unroll
        for (int i = 0; i < 8; ++i) Ws4[tid + i * 256] = W4[tid + i * 256];
        __syncthreads();
        const float* hb = hs + bq * RNN + c * 64;
#pragma unroll
        for (int r = 0; r < 64; ++r) acc = fmaf(hb[r], Ws[r * 128 + f], acc);
    }
    float s = tanhf(acc);
    float q = s * s;
#pragma unroll
    for (int o = 16; o > 0; o >>= 1) q += __shfl_xor_sync(0xffffffffu, q, o);
    int warp = tid >> 5, lane = tid & 31;
    if (lane == 0) red2[warp] = q;
    __syncthreads();
    float nrm = red2[bq * 4] + red2[bq * 4 + 1] + red2[bq * 4 + 2] + red2[bq * 4 + 3];
    g_scorer[(b0 + bq) * FF + f] = s * rsqrtf(nrm);
}

// --------------------------------------------------------------------------
// K2: scores[b,g] = node_embs[b,g,:] . scorer[b,:] + mask[b,g]
// --------------------------------------------------------------------------
__global__ void k2_scores(const float* __restrict__ ne,
                          const float* __restrict__ mask) {
    int b = blockIdx.x;
    int gbase = blockIdx.y * 64;
    __shared__ float4 sc[FF / 4];
    int tid = threadIdx.x;                   // 256
    if (tid < FF / 4)
        sc[tid] = reinterpret_cast<const float4*>(g_scorer + b * FF)[tid];
    __syncthreads();
    int warp = tid >> 5, lane = tid & 31;
    float4 s = sc[lane];
    const float4* base = reinterpret_cast<const float4*>(ne) + (size_t)b * GG * (FF / 4);
    int g0 = gbase + warp * 8;
    float d[8];
#pragma unroll
    for (int j = 0; j < 8; ++j) {
        float4 v = __ldcs(base + (size_t)(g0 + j) * (FF / 4) + lane);
        d[j] = v.x * s.x + v.y * s.y + v.z * s.z + v.w * s.w;
    }
#pragma unroll
    for (int o = 16; o > 0; o >>= 1) {
#pragma unroll
        for (int j = 0; j < 8; ++j) d[j] += __shfl_xor_sync(0xffffffffu, d[j], o);
    }
    if (lane == 0) {
        const float4* mb = reinterpret_cast<const float4*>(mask + b * GG + g0);
        float4* ob = reinterpret_cast<float4*>(g_scores + b * GG + g0);
        float4 m0 = mb[0], m1 = mb[1];
        ob[0] = make_float4(d[0] + m0.x, d[1] + m0.y, d[2] + m0.z, d[3] + m0.w);
        ob[1] = make_float4(d[4] + m1.x, d[5] + m1.y, d[6] + m1.z, d[7] + m1.w);
    }
}

// --------------------------------------------------------------------------
// K34 fused: radix-select top-128 + logsumexp + gather/transpose output.
// One block per batch, 512 threads. Tile in dynamic smem (128x129 floats).
// --------------------------------------------------------------------------
__device__ __forceinline__ unsigned f2u(float f) {
    unsigned u = __float_as_uint(f);
    return (u & 0x80000000u) ? ~u : (u | 0x80000000u);
}
__device__ __forceinline__ float u2f(unsigned u) {
    unsigned b = (u & 0x80000000u) ? (u & 0x7FFFFFFFu) : ~u;
    return __uint_as_float(b);
}

extern __shared__ float sm_tile[];       // 128*129 floats = 66048 B

__global__ void k34_topk_gather(const float* __restrict__ ne,
                                float* __restrict__ out,
                                float* __restrict__ policy_out) {
    const unsigned FULL = 0xffffffffu;
    int b = blockIdx.x, tid = threadIdx.x;   // 512 threads
    int lane = tid & 31, warp = tid >> 5;
    __shared__ float rbuf[16];
    __shared__ unsigned hist[256];
    __shared__ unsigned long long top[256];
    __shared__ float s_tv[KK];
    __shared__ int   s_ti[KK];
    __shared__ unsigned sel_d, sel_sub, cnt_;
    __shared__ float s_smax;

    // ---- load scores ----
    float v[4];
    unsigned u[4];
#pragma unroll
    for (int j = 0; j < 4; ++j) {
        v[j] = g_scores[b * GG + tid + j * 512];
        u[j] = f2u(v[j]);
    }

    // ---- radix select over 32-bit sortable value, 4x8-bit passes ----
    unsigned prefix = 0, kneed = KK;
    for (int shift = 24; shift >= 0; shift -= 8) {
        unsigned maskhi = (shift == 24) ? 0u : (0xFFFFFFFFu << (shift + 8));
        __syncthreads();
        if (tid < 256) hist[tid] = 0;
        __syncthreads();
#pragma unroll
        for (int j = 0; j < 4; ++j)
            if ((u[j] & maskhi) == prefix)
                atomicAdd(&hist[(u[j] >> shift) & 0xFFu], 1u);
        __syncthreads();
        if (tid < 32) {
            unsigned hv[8], t = 0;
#pragma unroll
            for (int q = 0; q < 8; ++q) { hv[q] = hist[tid * 8 + q]; t += hv[q]; }
            unsigned x = t;
#pragma unroll
            for (int o = 1; o < 32; o <<= 1) {
                unsigned y = __shfl_down_sync(FULL, x, o);
                if (tid + o < 32) x += y;
            }
            unsigned run = x - t;
#pragma unroll
            for (int q = 7; q >= 0; --q) { run += hv[q]; hist[tid * 8 + q] = run; }
        }
        __syncthreads();
        if (tid < 256) {
            unsigned h = hist[tid];
            unsigned hn = (tid == 255) ? 0u : hist[tid + 1];
            if (h >= kneed && hn < kneed) { sel_d = (unsigned)tid; sel_sub = hn; }
        }
        __syncthreads();
        prefix |= sel_d << shift;
        kneed -= sel_sub;
    }

    // ---- collect keys >= threshold ----
    if (tid == 0) cnt_ = 0;
    __syncthreads();
#pragma unroll
    for (int j = 0; j < 4; ++j) {
        if (u[j] >= prefix) {
            unsigned p = atomicAdd(&cnt_, 1u);
            if (p < 256)
                top[p] = ((unsigned long long)u[j] << 32) |
                         (unsigned)(~(unsigned)(tid + j * 512));
        }
    }
    __syncthreads();
    unsigned n = cnt_ < 256u ? cnt_ : 256u;

    // ---- rank by counting (value desc, index asc), keep results in smem ----
    float contrib = 0.f;
    if (tid < (int)n) {
        unsigned long long key = top[tid];
        unsigned r = 0;
        for (unsigned jj = 0; jj < n; ++jj) r += (top[jj] > key);
        if (r < KK) {
            float val = u2f((unsigned)(key >> 32));
            s_tv[r] = tanhf(val);
            s_ti[r] = (int)(~(unsigned)key);
            contrib = val;
            if (r == 0) s_smax = val;
        }
    }
#pragma unroll
    for (int o = 16; o > 0; o >>= 1) contrib += __shfl_xor_sync(FULL, contrib, o);
    if (lane == 0) rbuf[warp] = contrib;
    __syncthreads();
    float sumtop = 0.f;
    if (tid == 0) {
#pragma unroll
        for (int w = 0; w < 16; ++w) sumtop += rbuf[w];
    }
    float smax = s_smax;
    __syncthreads();

    // ---- sum exp + policy ----
    float sum = expf(v[0] - smax) + expf(v[1] - smax) +
                expf(v[2] - smax) + expf(v[3] - smax);
#pragma unroll
    for (int o = 16; o > 0; o >>= 1) sum += __shfl_xor_sync(FULL, sum, o);
    if (lane == 0) rbuf[warp] = sum;
    __syncthreads();
    if (tid == 0) {
        float x = 0.f;
#pragma unroll
        for (int w = 0; w < 16; ++w) x += rbuf[w];
        policy_out[b] = sumtop * (1.0f / KK) - (smax + logf(x));
    }

    // ================= gather + transpose (128 rows, one pass) ============
    const float4* base = reinterpret_cast<const float4*>(ne) + (size_t)b * GG * (FF / 4);
    float* ob = out + (size_t)b * FF * KK;
    // 8 front-batched LDG.128 per thread; coalesced 512B per gathered row
#pragma unroll
    for (int it = 0; it < 8; ++it) {
        int i = tid + it * 512;              // 0..4095
        int k = i >> 5, c = i & 31;
        float4 vv = base[(size_t)s_ti[k] * (FF / 4) + c];
        float s = s_tv[k];
        float* t = sm_tile + k * 129 + c * 4;
        t[0] = vv.x * s; t[1] = vv.y * s; t[2] = vv.z * s; t[3] = vv.w * s;
    }
    __syncthreads();
    // transposed writes: conflict-free LDS, 128B-coalesced STG.128
#pragma unroll
    for (int sub = 0; sub < 4; ++sub) {
        int k0 = sub * 32;
#pragma unroll
        for (int it = 0; it < 2; ++it) {
            int i = tid + it * 512;          // 0..1023
            int f = i >> 3, q = i & 7;
            int k = q * 4;
            const float* t = sm_tile + (k0 + k) * 129 + f;
            float4 w;
            w.x = t[0 * 129];
            w.y = t[1 * 129];
            w.z = t[2 * 129];
            w.w = t[3 * 129];
            *reinterpret_cast<float4*>(ob + (size_t)f * KK + k0 + k) = w;
        }
    }
}

// --------------------------------------------------------------------------
extern "C" void kernel_launch(void* const* d_in, const int* in_sizes, int n_in,
                              void* d_out, int out_size) {
    const float* node_embs = (const float*)d_in[0];
    const float* mask      = (const float*)d_in[1];
    const float* h_t       = (const float*)d_in[2];
    const float* W_map     = (const float*)d_in[3];
    const float* b_map     = (const float*)d_in[4];
    float* out    = (float*)d_out;
    float* policy = out + (size_t)BB * FF * KK;   // outputs: [B,F,K] then [B]

    const int tile_bytes = 128 * 129 * sizeof(float);   // 66048
    cudaFuncSetAttribute(k34_topk_gather,
                         cudaFuncAttributeMaxDynamicSharedMemorySize, tile_bytes);

    k1_scorer<<<BB / 2, 256>>>(h_t, W_map, b_map);
    k2_scores<<<dim3(BB, GG / 64), 256>>>(node_embs, mask);
    k34_topk_gather<<<BB, 512, tile_bytes>>>(node_embs, out, policy);
}